// round 5
// baseline (speedup 1.0000x reference)
#include <cuda_runtime.h>
#include <cuda_bf16.h>
#include <cuda_fp16.h>
#include <math_constants.h>

#define VV 3
#define BB 2
#define CC 16
#define HH 128
#define WW 128
#define DD 32
#define HWSZ (HH*WW)
#define NQ 4                       // 16 channels as 4 x float4 chunks (fp32)

// Scratch (device globals; no runtime allocation)
__device__ float g_proj[(VV-1)*BB*12];
// fp32 chunk-planar features: (vb*NQ + q)*HWSZ + pix
__device__ float4 g_feat[(size_t)VV*BB*NQ*HWSZ];
// fp16 chunk-planar features: (vb*2 + q2)*HWSZ + pix, uint4 = 8 halves
__device__ uint4 g_feath[(size_t)VV*BB*2*HWSZ];
__device__ float g_cost[(size_t)BB*DD*HWSZ];           // min cost volume (b,d,pix)
__device__ float g_wfeat[(size_t)25*BB*HWSZ];          // feature weights [k][b][pix]
__device__ float g_agg[(size_t)BB*DD*HWSZ];            // aggregated costs (b,d,pix)

// ---------------------------------------------------------------------------
// K0: projection matrices  proj = M_src @ inv(M_ref)
// ---------------------------------------------------------------------------
__device__ void mat3_inv_d(const double* A, double* o) {
    double c00 = A[4]*A[8]-A[5]*A[7];
    double c01 = A[5]*A[6]-A[3]*A[8];
    double c02 = A[3]*A[7]-A[4]*A[6];
    double det = A[0]*c00 + A[1]*c01 + A[2]*c02;
    double id = 1.0/det;
    o[0]=c00*id;                  o[1]=(A[2]*A[7]-A[1]*A[8])*id; o[2]=(A[1]*A[5]-A[2]*A[4])*id;
    o[3]=c01*id;                  o[4]=(A[0]*A[8]-A[2]*A[6])*id; o[5]=(A[2]*A[3]-A[0]*A[5])*id;
    o[6]=c02*id;                  o[7]=(A[1]*A[6]-A[0]*A[7])*id; o[8]=(A[0]*A[4]-A[1]*A[3])*id;
}

__device__ void build_M(const float* intr, const float* c2w, int vb,
                        double* Afull, double* bfull) {
    double K[9], R[9], t[3];
    #pragma unroll
    for (int i = 0; i < 3; i++) {
        #pragma unroll
        for (int j = 0; j < 3; j++) {
            K[i*3+j] = (double)intr[(vb*3+i)*3+j];
            R[i*3+j] = (double)c2w[(vb*4+i)*4+j];
        }
        t[i] = (double)c2w[(vb*4+i)*4+3];
    }
    double bb[3];
    #pragma unroll
    for (int i = 0; i < 3; i++)
        bb[i] = -(R[0*3+i]*t[0] + R[1*3+i]*t[1] + R[2*3+i]*t[2]);
    #pragma unroll
    for (int i = 0; i < 3; i++) {
        #pragma unroll
        for (int j = 0; j < 3; j++)
            Afull[i*3+j] = K[i*3+0]*R[j*3+0] + K[i*3+1]*R[j*3+1] + K[i*3+2]*R[j*3+2];
        bfull[i] = K[i*3+0]*bb[0] + K[i*3+1]*bb[1] + K[i*3+2]*bb[2] + bb[i];
    }
}

__global__ void proj_kernel(const float* __restrict__ intr,
                            const float* __restrict__ c2w) {
    int t = threadIdx.x;
    if (t >= (VV-1)*BB) return;
    int v = t / BB + 1;
    int b = t % BB;

    double As[9], bs[3], Ar[9], br[3];
    build_M(intr, c2w, v*BB + b, As, bs);
    build_M(intr, c2w, 0*BB + b, Ar, br);

    double Ainv[9];
    mat3_inv_d(Ar, Ainv);
    double binv[3];
    #pragma unroll
    for (int i = 0; i < 3; i++)
        binv[i] = -(Ainv[i*3+0]*br[0] + Ainv[i*3+1]*br[1] + Ainv[i*3+2]*br[2]);

    float* P = g_proj + t*12;
    #pragma unroll
    for (int i = 0; i < 3; i++) {
        #pragma unroll
        for (int j = 0; j < 3; j++)
            P[i*3+j] = (float)(As[i*3+0]*Ainv[0*3+j] + As[i*3+1]*Ainv[1*3+j] + As[i*3+2]*Ainv[2*3+j]);
        P[9+i] = (float)(As[i*3+0]*binv[0] + As[i*3+1]*binv[1] + As[i*3+2]*binv[2] + bs[i]);
    }
}

// ---------------------------------------------------------------------------
// K1: transpose features -> fp32 chunk-planar + fp16 chunk-planar
// ---------------------------------------------------------------------------
__global__ void nhwc_kernel(const float* __restrict__ feat) {
    int idx = blockIdx.x * blockDim.x + threadIdx.x;
    if (idx >= VV*BB*HWSZ) return;
    int pix = idx & (HWSZ-1);
    int vb  = idx >> 14;
    const float* in = feat + (size_t)vb*CC*HWSZ + pix;
    float v[16];
    #pragma unroll
    for (int c = 0; c < 16; c++) v[c] = in[(size_t)c*HWSZ];

    #pragma unroll
    for (int q = 0; q < NQ; q++)
        g_feat[((size_t)(vb*NQ + q))*HWSZ + pix] =
            make_float4(v[q*4+0], v[q*4+1], v[q*4+2], v[q*4+3]);

    #pragma unroll
    for (int q2 = 0; q2 < 2; q2++) {
        __half2 h0 = __floats2half2_rn(v[q2*8+0], v[q2*8+1]);
        __half2 h1 = __floats2half2_rn(v[q2*8+2], v[q2*8+3]);
        __half2 h2 = __floats2half2_rn(v[q2*8+4], v[q2*8+5]);
        __half2 h3 = __floats2half2_rn(v[q2*8+6], v[q2*8+7]);
        uint4 raw;
        raw.x = *reinterpret_cast<unsigned int*>(&h0);
        raw.y = *reinterpret_cast<unsigned int*>(&h1);
        raw.z = *reinterpret_cast<unsigned int*>(&h2);
        raw.w = *reinterpret_cast<unsigned int*>(&h3);
        g_feath[((size_t)(vb*2 + q2))*HWSZ + pix] = raw;
    }
}

// ---------------------------------------------------------------------------
// K2: feature weights, smem-tiled (fp32). Block = 16x16 pixels, halo 20x20.
// ---------------------------------------------------------------------------
#define TS 16
#define THALO 20
__global__ void __launch_bounds__(256)
wfeat_kernel() {
    __shared__ float4 sf[NQ][THALO*THALO];

    int bx = blockIdx.x, by = blockIdx.y, b = blockIdx.z;
    int tid = threadIdx.x;
    int tx = tid & (TS-1), ty = tid >> 4;

    int ox = bx*TS - 2, oy = by*TS - 2;

    for (int i = tid; i < THALO*THALO; i += 256) {
        int ly = i / THALO, lx = i - ly*THALO;
        int gy = oy + ly, gx = ox + lx;
        if ((unsigned)gy < (unsigned)HH && (unsigned)gx < (unsigned)WW) {
            int gp = (gy<<7) + gx;
            #pragma unroll
            for (int q = 0; q < NQ; q++)
                sf[q][i] = g_feat[((size_t)(b*NQ + q))*HWSZ + gp];
        }
    }
    __syncthreads();

    int x = bx*TS + tx, y = by*TS + ty;
    int pix = (y<<7) + x;
    int lc = (ty+2)*THALO + (tx+2);

    float fc[16];
    #pragma unroll
    for (int q = 0; q < NQ; q++) {
        float4 a = sf[q][lc];
        fc[q*4+0]=a.x; fc[q*4+1]=a.y; fc[q*4+2]=a.z; fc[q*4+3]=a.w;
    }

    #pragma unroll
    for (int k = 0; k < 25; k++) {
        int di = k/5, dj = k%5;
        int ny = y + di - 2, nx = x + dj - 2;
        float w = 0.0f;
        if ((unsigned)ny < (unsigned)HH && (unsigned)nx < (unsigned)WW) {
            int ln = (ty+di)*THALO + (tx+dj);
            float s = 0.0f;
            #pragma unroll
            for (int q = 0; q < NQ; q++) {
                float4 c = sf[q][ln];
                float d0 = fc[q*4+0]-c.x, d1 = fc[q*4+1]-c.y;
                float d2 = fc[q*4+2]-c.z, d3 = fc[q*4+3]-c.w;
                s += d0*d0 + d1*d1 + d2*d2 + d3*d3;
            }
            w = sqrtf(s);
        }
        g_wfeat[((size_t)k*BB + b)*HWSZ + pix] = w;
    }
}

// ---------------------------------------------------------------------------
// K3: homography warp + bilinear sample (fp16 src) + cumsum cost + min
// ---------------------------------------------------------------------------
__global__ void __launch_bounds__(256)
warp_cost_kernel(const float* __restrict__ depth_hypo) {
    int idx = blockIdx.x * blockDim.x + threadIdx.x;
    if (idx >= BB*DD*HWSZ) return;
    int x = idx & 127;
    int y = (idx >> 7) & 127;
    int b = idx >> 19;
    int pix = idx & (HWSZ-1);

    float depth = depth_hypo[idx];

    // ref features fp32 (precise, contiguous)
    float rv[16];
    #pragma unroll
    for (int q = 0; q < NQ; q++) {
        float4 r = g_feat[((size_t)(b*NQ + q))*HWSZ + pix];
        rv[q*4+0] = r.x; rv[q*4+1] = r.y; rv[q*4+2] = r.z; rv[q*4+3] = r.w;
    }

    float cum[16];
    #pragma unroll
    for (int c = 0; c < 16; c++) cum[c] = 0.0f;

    const float SXY = (float)WW / (float)(WW-1);
    float fxp = (float)x, fyp = (float)y;
    float cost_min = CUDART_INF_F;

    #pragma unroll
    for (int v = 0; v < VV-1; v++) {
        const float* P = g_proj + (v*BB + b)*12;
        float X = (P[0]*fxp + P[1]*fyp + P[2])*depth + P[9];
        float Y = (P[3]*fxp + P[4]*fyp + P[5])*depth + P[10];
        float Z = (P[6]*fxp + P[7]*fyp + P[8])*depth + P[11];
        float px = __fdividef(X, Z) * SXY - 0.5f;
        float py = __fdividef(Y, Z) * SXY - 0.5f;
        float x0f = floorf(px), y0f = floorf(py);
        float tx = px - x0f, ty = py - y0f;
        int x0 = (int)x0f, y0 = (int)y0f;

        float w00 = (1.0f-tx)*(1.0f-ty);
        float w01 = tx*(1.0f-ty);
        float w10 = (1.0f-tx)*ty;
        float w11 = tx*ty;

        const uint4* sbh = g_feath + ((size_t)((v+1)*BB + b)*2)*HWSZ;

        int xs[4] = {x0, x0+1, x0, x0+1};
        int ys[4] = {y0, y0, y0+1, y0+1};
        float ws[4] = {w00, w01, w10, w11};
        #pragma unroll
        for (int tap = 0; tap < 4; tap++) {
            int xi = xs[tap], yi = ys[tap];
            if ((unsigned)xi < (unsigned)WW && (unsigned)yi < (unsigned)HH) {
                int sp = (yi<<7) + xi;
                float w = ws[tap];
                #pragma unroll
                for (int q2 = 0; q2 < 2; q2++) {
                    uint4 raw = sbh[(size_t)q2*HWSZ + sp];
                    float2 f0 = __half22float2(*reinterpret_cast<__half2*>(&raw.x));
                    float2 f1 = __half22float2(*reinterpret_cast<__half2*>(&raw.y));
                    float2 f2 = __half22float2(*reinterpret_cast<__half2*>(&raw.z));
                    float2 f3 = __half22float2(*reinterpret_cast<__half2*>(&raw.w));
                    cum[q2*8+0] += w*f0.x; cum[q2*8+1] += w*f0.y;
                    cum[q2*8+2] += w*f1.x; cum[q2*8+3] += w*f1.y;
                    cum[q2*8+4] += w*f2.x; cum[q2*8+5] += w*f2.y;
                    cum[q2*8+6] += w*f3.x; cum[q2*8+7] += w*f3.y;
                }
            }
        }

        float s = 0.0f;
        #pragma unroll
        for (int c = 0; c < 16; c++) {
            float dlt = rv[c] - cum[c];
            s += dlt*dlt;
        }
        cost_min = fminf(cost_min, sqrtf(s));
    }
    g_cost[idx] = cost_min;
}

// ---------------------------------------------------------------------------
// K4: aggregation, smem-tiled. Block = 16x16 pixels for one (b,d).
// ---------------------------------------------------------------------------
__global__ void __launch_bounds__(256)
aggd_kernel(const float* __restrict__ depth_hypo) {
    __shared__ float sd[THALO*THALO];
    __shared__ float sc[THALO*THALO];

    int bx = blockIdx.x, by = blockIdx.y, bd = blockIdx.z;
    int b = bd / DD;
    int tid = threadIdx.x;
    int tx = tid & (TS-1), ty = tid >> 4;

    const float* dsl = depth_hypo + (size_t)bd*HWSZ;
    const float* csl = g_cost     + (size_t)bd*HWSZ;

    int ox = bx*TS - 2, oy = by*TS - 2;
    for (int i = tid; i < THALO*THALO; i += 256) {
        int ly = i / THALO, lx = i - ly*THALO;
        int gy = oy + ly, gx = ox + lx;
        bool inb = (unsigned)gy < (unsigned)HH && (unsigned)gx < (unsigned)WW;
        int gp = (gy<<7) + gx;
        sd[i] = inb ? dsl[gp] : 0.0f;
        sc[i] = inb ? csl[gp] : 0.0f;
    }
    __syncthreads();

    int x = bx*TS + tx, y = by*TS + ty;
    int pix = (y<<7) + x;

    float dc = sd[(ty+2)*THALO + (tx+2)];
    const float* wfb = g_wfeat + (size_t)b*HWSZ + pix;

    float esum = 0.0f, acc = 0.0f;
    #pragma unroll
    for (int k = 0; k < 25; k++) {
        int di = k/5, dj = k%5;
        int ny = y + di - 2, nx = x + dj - 2;
        bool inb = (unsigned)ny < (unsigned)HH && (unsigned)nx < (unsigned)WW;
        int ln = (ty+di)*THALO + (tx+dj);
        float dn = sd[ln];
        float e = __expf(fabsf(dn - dc));
        esum += e;
        if (inb) {
            float cn = sc[ln];
            float wf = wfb[(size_t)k * (BB*HWSZ)];
            acc += cn * e * wf;
        }
    }
    g_agg[(size_t)bd*HWSZ + pix] = __fdividef(acc, esum);
}

// ---------------------------------------------------------------------------
// K5: softmax over D + depth expectation, per (b,pix)
// ---------------------------------------------------------------------------
__global__ void __launch_bounds__(128)
expect_kernel(const float* __restrict__ depth_hypo,
              float* __restrict__ out) {
    int idx = blockIdx.x * blockDim.x + threadIdx.x;
    if (idx >= BB*HWSZ) return;
    int pix = idx & (HWSZ-1);
    int b   = idx >> 14;

    const float* ab = g_agg      + (size_t)b*DD*HWSZ + pix;
    const float* db = depth_hypo + (size_t)b*DD*HWSZ + pix;

    float ag[DD], dv[DD];
    float m = -CUDART_INF_F;
    #pragma unroll
    for (int d = 0; d < DD; d++) {
        ag[d] = ab[(size_t)d*HWSZ];
        dv[d] = db[(size_t)d*HWSZ];
        m = fmaxf(m, ag[d]);
    }
    float ssum = 0.0f, tsum = 0.0f;
    #pragma unroll
    for (int d = 0; d < DD; d++) {
        float e = __expf(ag[d] - m);
        ssum += e;
        tsum += e * dv[d];
    }
    out[idx] = __fdividef(tsum, ssum);
}

// ---------------------------------------------------------------------------
extern "C" void kernel_launch(void* const* d_in, const int* in_sizes, int n_in,
                              void* d_out, int out_size) {
    const float* features   = (const float*)d_in[0];  // (3,2,16,128,128)
    const float* intrinsics = (const float*)d_in[1];  // (3,2,3,3)
    const float* cam2world  = (const float*)d_in[2];  // (3,2,4,4)
    const float* depth_hypo = (const float*)d_in[3];  // (2,32,128,128)
    float* out = (float*)d_out;                       // (2,128,128)

    proj_kernel<<<1, 32>>>(intrinsics, cam2world);

    {
        int n = VV*BB*HWSZ;
        nhwc_kernel<<<(n + 255)/256, 256>>>(features);
    }
    {
        dim3 g(WW/TS, HH/TS, BB);
        wfeat_kernel<<<g, 256>>>();
    }
    {
        int n = BB*DD*HWSZ;
        warp_cost_kernel<<<(n + 255)/256, 256>>>(depth_hypo);
    }
    {
        dim3 g(WW/TS, HH/TS, BB*DD);
        aggd_kernel<<<g, 256>>>(depth_hypo);
    }
    {
        int n = BB*HWSZ;
        expect_kernel<<<(n + 127)/128, 128>>>(depth_hypo, out);
    }
}

// round 6
// speedup vs baseline: 1.6064x; 1.6064x over previous
#include <cuda_runtime.h>
#include <cuda_bf16.h>
#include <cuda_fp16.h>
#include <math_constants.h>

#define VV 3
#define BB 2
#define CC 16
#define HH 128
#define WW 128
#define DD 32
#define HWSZ (HH*WW)
#define NQ 4

// Scratch (device globals; no runtime allocation)
__device__ float g_proj[(VV-1)*BB*12];
__device__ float4 g_feat[(size_t)VV*BB*NQ*HWSZ];        // fp32 chunk-planar (wfeat)
__device__ uint4 g_feath[(size_t)VV*BB*2*HWSZ];         // fp16 chunk-planar (warp)
__device__ float g_cost[(size_t)BB*DD*HWSZ];            // min cost volume
__device__ float g_wfeat[(size_t)25*BB*HWSZ];           // [k][b][pix]
__device__ float g_part[(size_t)BB*4*3*HWSZ];           // partial softmax (m,S,T) per chunk

// ---------------------------------------------------------------------------
// K0: projection matrices
// ---------------------------------------------------------------------------
__device__ void mat3_inv_d(const double* A, double* o) {
    double c00 = A[4]*A[8]-A[5]*A[7];
    double c01 = A[5]*A[6]-A[3]*A[8];
    double c02 = A[3]*A[7]-A[4]*A[6];
    double det = A[0]*c00 + A[1]*c01 + A[2]*c02;
    double id = 1.0/det;
    o[0]=c00*id;                  o[1]=(A[2]*A[7]-A[1]*A[8])*id; o[2]=(A[1]*A[5]-A[2]*A[4])*id;
    o[3]=c01*id;                  o[4]=(A[0]*A[8]-A[2]*A[6])*id; o[5]=(A[2]*A[3]-A[0]*A[5])*id;
    o[6]=c02*id;                  o[7]=(A[1]*A[6]-A[0]*A[7])*id; o[8]=(A[0]*A[4]-A[1]*A[3])*id;
}

__device__ void build_M(const float* intr, const float* c2w, int vb,
                        double* Afull, double* bfull) {
    double K[9], R[9], t[3];
    #pragma unroll
    for (int i = 0; i < 3; i++) {
        #pragma unroll
        for (int j = 0; j < 3; j++) {
            K[i*3+j] = (double)intr[(vb*3+i)*3+j];
            R[i*3+j] = (double)c2w[(vb*4+i)*4+j];
        }
        t[i] = (double)c2w[(vb*4+i)*4+3];
    }
    double bb[3];
    #pragma unroll
    for (int i = 0; i < 3; i++)
        bb[i] = -(R[0*3+i]*t[0] + R[1*3+i]*t[1] + R[2*3+i]*t[2]);
    #pragma unroll
    for (int i = 0; i < 3; i++) {
        #pragma unroll
        for (int j = 0; j < 3; j++)
            Afull[i*3+j] = K[i*3+0]*R[j*3+0] + K[i*3+1]*R[j*3+1] + K[i*3+2]*R[j*3+2];
        bfull[i] = K[i*3+0]*bb[0] + K[i*3+1]*bb[1] + K[i*3+2]*bb[2] + bb[i];
    }
}

__global__ void proj_kernel(const float* __restrict__ intr,
                            const float* __restrict__ c2w) {
    int t = threadIdx.x;
    if (t >= (VV-1)*BB) return;
    int v = t / BB + 1;
    int b = t % BB;

    double As[9], bs[3], Ar[9], br[3];
    build_M(intr, c2w, v*BB + b, As, bs);
    build_M(intr, c2w, 0*BB + b, Ar, br);

    double Ainv[9];
    mat3_inv_d(Ar, Ainv);
    double binv[3];
    #pragma unroll
    for (int i = 0; i < 3; i++)
        binv[i] = -(Ainv[i*3+0]*br[0] + Ainv[i*3+1]*br[1] + Ainv[i*3+2]*br[2]);

    float* P = g_proj + t*12;
    #pragma unroll
    for (int i = 0; i < 3; i++) {
        #pragma unroll
        for (int j = 0; j < 3; j++)
            P[i*3+j] = (float)(As[i*3+0]*Ainv[0*3+j] + As[i*3+1]*Ainv[1*3+j] + As[i*3+2]*Ainv[2*3+j]);
        P[9+i] = (float)(As[i*3+0]*binv[0] + As[i*3+1]*binv[1] + As[i*3+2]*binv[2] + bs[i]);
    }
}

// ---------------------------------------------------------------------------
// K1: transpose features -> fp32 chunk-planar + fp16 chunk-planar
// ---------------------------------------------------------------------------
__global__ void nhwc_kernel(const float* __restrict__ feat) {
    int idx = blockIdx.x * blockDim.x + threadIdx.x;
    if (idx >= VV*BB*HWSZ) return;
    int pix = idx & (HWSZ-1);
    int vb  = idx >> 14;
    const float* in = feat + (size_t)vb*CC*HWSZ + pix;
    float v[16];
    #pragma unroll
    for (int c = 0; c < 16; c++) v[c] = in[(size_t)c*HWSZ];

    #pragma unroll
    for (int q = 0; q < NQ; q++)
        g_feat[((size_t)(vb*NQ + q))*HWSZ + pix] =
            make_float4(v[q*4+0], v[q*4+1], v[q*4+2], v[q*4+3]);

    #pragma unroll
    for (int q2 = 0; q2 < 2; q2++) {
        __half2 h0 = __floats2half2_rn(v[q2*8+0], v[q2*8+1]);
        __half2 h1 = __floats2half2_rn(v[q2*8+2], v[q2*8+3]);
        __half2 h2 = __floats2half2_rn(v[q2*8+4], v[q2*8+5]);
        __half2 h3 = __floats2half2_rn(v[q2*8+6], v[q2*8+7]);
        uint4 raw;
        raw.x = *reinterpret_cast<unsigned int*>(&h0);
        raw.y = *reinterpret_cast<unsigned int*>(&h1);
        raw.z = *reinterpret_cast<unsigned int*>(&h2);
        raw.w = *reinterpret_cast<unsigned int*>(&h3);
        g_feath[((size_t)(vb*2 + q2))*HWSZ + pix] = raw;
    }
}

// ---------------------------------------------------------------------------
// K2: feature weights, smem-tiled (fp32)
// ---------------------------------------------------------------------------
#define TS 16
#define THALO 20
__global__ void __launch_bounds__(256)
wfeat_kernel() {
    __shared__ float4 sf[NQ][THALO*THALO];

    int bx = blockIdx.x, by = blockIdx.y, b = blockIdx.z;
    int tid = threadIdx.x;
    int tx = tid & (TS-1), ty = tid >> 4;

    int ox = bx*TS - 2, oy = by*TS - 2;

    for (int i = tid; i < THALO*THALO; i += 256) {
        int ly = i / THALO, lx = i - ly*THALO;
        int gy = oy + ly, gx = ox + lx;
        if ((unsigned)gy < (unsigned)HH && (unsigned)gx < (unsigned)WW) {
            int gp = (gy<<7) + gx;
            #pragma unroll
            for (int q = 0; q < NQ; q++)
                sf[q][i] = g_feat[((size_t)(b*NQ + q))*HWSZ + gp];
        }
    }
    __syncthreads();

    int x = bx*TS + tx, y = by*TS + ty;
    int pix = (y<<7) + x;
    int lc = (ty+2)*THALO + (tx+2);

    float fc[16];
    #pragma unroll
    for (int q = 0; q < NQ; q++) {
        float4 a = sf[q][lc];
        fc[q*4+0]=a.x; fc[q*4+1]=a.y; fc[q*4+2]=a.z; fc[q*4+3]=a.w;
    }

    #pragma unroll
    for (int k = 0; k < 25; k++) {
        int di = k/5, dj = k%5;
        int ny = y + di - 2, nx = x + dj - 2;
        float w = 0.0f;
        if ((unsigned)ny < (unsigned)HH && (unsigned)nx < (unsigned)WW) {
            int ln = (ty+di)*THALO + (tx+dj);
            float s = 0.0f;
            #pragma unroll
            for (int q = 0; q < NQ; q++) {
                float4 c = sf[q][ln];
                float d0 = fc[q*4+0]-c.x, d1 = fc[q*4+1]-c.y;
                float d2 = fc[q*4+2]-c.z, d3 = fc[q*4+3]-c.w;
                s += d0*d0 + d1*d1 + d2*d2 + d3*d3;
            }
            w = sqrtf(s);
        }
        g_wfeat[((size_t)k*BB + b)*HWSZ + pix] = w;
    }
}

// ---------------------------------------------------------------------------
// K3: warp + bilinear (half2 HFMA2 accumulation), 2 depths per thread
// ---------------------------------------------------------------------------
__global__ void __launch_bounds__(256)
warp_cost_kernel(const float* __restrict__ depth_hypo) {
    int t = blockIdx.x * blockDim.x + threadIdx.x;     // over B * (D/2) * HWSZ
    if (t >= BB*(DD/2)*HWSZ) return;
    int pix = t & (HWSZ-1);
    int d2  = (t >> 14) & 15;
    int b   = t >> 18;
    int x = pix & 127, y = pix >> 7;

    int idx0 = ((b*DD + d2) << 14) | pix;
    int idx1 = idx0 + (16 << 14);
    float dep[2] = {depth_hypo[idx0], depth_hypo[idx1]};

    // ref features fp16 (coalesced)
    uint4 refr[2];
    refr[0] = g_feath[(size_t)(b*2+0)*HWSZ + pix];
    refr[1] = g_feath[(size_t)(b*2+1)*HWSZ + pix];
    float rv[16];
    #pragma unroll
    for (int q2 = 0; q2 < 2; q2++) {
        const unsigned int* rr = &refr[q2].x;
        #pragma unroll
        for (int j = 0; j < 4; j++) {
            float2 f = __half22float2(*reinterpret_cast<const __half2*>(&rr[j]));
            rv[q2*8+j*2+0] = f.x; rv[q2*8+j*2+1] = f.y;
        }
    }

    const float SXY = (float)WW / (float)(WW-1);
    float fxp = (float)x, fyp = (float)y;

    __half2 cum[2][8];
    #pragma unroll
    for (int p = 0; p < 2; p++)
        #pragma unroll
        for (int j = 0; j < 8; j++) cum[p][j] = __half2half2(__ushort_as_half(0));

    float cmin[2] = {CUDART_INF_F, CUDART_INF_F};

    #pragma unroll
    for (int v = 0; v < VV-1; v++) {
        const float* P = g_proj + (v*BB + b)*12;
        float rx = P[0]*fxp + P[1]*fyp + P[2];
        float ry = P[3]*fxp + P[4]*fyp + P[5];
        float rz = P[6]*fxp + P[7]*fyp + P[8];
        const uint4* sbh = g_feath + ((size_t)((v+1)*BB + b)*2)*HWSZ;

        #pragma unroll
        for (int p = 0; p < 2; p++) {
            float depth = dep[p];
            float X = rx*depth + P[9];
            float Y = ry*depth + P[10];
            float Z = rz*depth + P[11];
            float px = __fdividef(X, Z) * SXY - 0.5f;
            float py = __fdividef(Y, Z) * SXY - 0.5f;
            float x0f = floorf(px), y0f = floorf(py);
            float tx = px - x0f, ty = py - y0f;
            int x0 = (int)x0f, y0 = (int)y0f;

            float ws[4] = {(1.0f-tx)*(1.0f-ty), tx*(1.0f-ty),
                           (1.0f-tx)*ty,        tx*ty};
            int xs[4] = {x0, x0+1, x0, x0+1};
            int ys[4] = {y0, y0, y0+1, y0+1};

            #pragma unroll
            for (int tap = 0; tap < 4; tap++) {
                int xi = xs[tap], yi = ys[tap];
                if ((unsigned)xi < (unsigned)WW && (unsigned)yi < (unsigned)HH) {
                    int sp = (yi<<7) + xi;
                    __half2 wh = __float2half2_rn(ws[tap]);
                    #pragma unroll
                    for (int q2 = 0; q2 < 2; q2++) {
                        uint4 raw = sbh[(size_t)q2*HWSZ + sp];
                        const unsigned int* rr = &raw.x;
                        #pragma unroll
                        for (int j = 0; j < 4; j++)
                            cum[p][q2*4+j] = __hfma2(wh,
                                *reinterpret_cast<const __half2*>(&rr[j]),
                                cum[p][q2*4+j]);
                    }
                }
            }
        }

        // cost at this cumsum level for both depth points
        #pragma unroll
        for (int p = 0; p < 2; p++) {
            float s = 0.0f;
            #pragma unroll
            for (int j = 0; j < 8; j++) {
                float2 c = __half22float2(cum[p][j]);
                float d0 = rv[j*2+0] - c.x;
                float d1 = rv[j*2+1] - c.y;
                s += d0*d0 + d1*d1;
            }
            cmin[p] = fminf(cmin[p], sqrtf(s));
        }
    }
    g_cost[idx0] = cmin[0];
    g_cost[idx1] = cmin[1];
}

// ---------------------------------------------------------------------------
// K4: tile x 8-depth chunk: aggregation + partial online softmax over D
// ---------------------------------------------------------------------------
#define DCH 8
__global__ void __launch_bounds__(256)
agg_part_kernel(const float* __restrict__ depth_hypo) {
    __shared__ float sd[THALO*THALO];
    __shared__ float sc[THALO*THALO];

    int bx = blockIdx.x, by = blockIdx.y, bz = blockIdx.z;  // bz over B*4
    int b = bz >> 2, ch = bz & 3;
    int tid = threadIdx.x;
    int tx = tid & (TS-1), ty = tid >> 4;

    int x = bx*TS + tx, y = by*TS + ty;
    int pix = (y<<7) + x;
    int ox = bx*TS - 2, oy = by*TS - 2;

    // per-thread feature weights (amortized over DCH depths)
    float wf[25];
    #pragma unroll
    for (int k = 0; k < 25; k++)
        wf[k] = g_wfeat[((size_t)k*BB + b)*HWSZ + pix];

    float m = -CUDART_INF_F, ss = 0.0f, ts = 0.0f;

    for (int dd = 0; dd < DCH; dd++) {
        int d = ch*DCH + dd;
        const float* dsl = depth_hypo + (size_t)(b*DD + d)*HWSZ;
        const float* csl = g_cost     + (size_t)(b*DD + d)*HWSZ;

        if (dd) __syncthreads();
        for (int i = tid; i < THALO*THALO; i += 256) {
            int ly = i / THALO, lx = i - ly*THALO;
            int gy = oy + ly, gx = ox + lx;
            bool inb = (unsigned)gy < (unsigned)HH && (unsigned)gx < (unsigned)WW;
            int gp = (gy<<7) + gx;
            sd[i] = inb ? dsl[gp] : 0.0f;
            sc[i] = inb ? csl[gp] : 0.0f;
        }
        __syncthreads();

        float dc = sd[(ty+2)*THALO + (tx+2)];
        float esum = 0.0f, acc = 0.0f;
        #pragma unroll
        for (int k = 0; k < 25; k++) {
            int di = k/5, dj = k%5;
            int ny = y + di - 2, nx = x + dj - 2;
            bool inb = (unsigned)ny < (unsigned)HH && (unsigned)nx < (unsigned)WW;
            int ln = (ty+di)*THALO + (tx+dj);
            float e = __expf(fabsf(sd[ln] - dc));
            esum += e;
            if (inb) acc += sc[ln] * e * wf[k];
        }
        float agg = __fdividef(acc, esum);

        float nm = fmaxf(m, agg);
        float scale = __expf(m - nm);    // first iter: 0
        float ea = __expf(agg - nm);
        ss = ss * scale + ea;
        ts = ts * scale + ea * dc;
        m = nm;
    }

    size_t base = (size_t)bz*3*HWSZ + pix;
    g_part[base + 0*HWSZ] = m;
    g_part[base + 1*HWSZ] = ss;
    g_part[base + 2*HWSZ] = ts;
}

// ---------------------------------------------------------------------------
// K5: combine 4 chunk partials -> depth expectation
// ---------------------------------------------------------------------------
__global__ void __launch_bounds__(256)
combine_kernel(float* __restrict__ out) {
    int idx = blockIdx.x * blockDim.x + threadIdx.x;   // over B*HWSZ
    if (idx >= BB*HWSZ) return;
    int pix = idx & (HWSZ-1);
    int b   = idx >> 14;

    float mv[4], sv[4], tv[4];
    float M = -CUDART_INF_F;
    #pragma unroll
    for (int c = 0; c < 4; c++) {
        size_t base = (size_t)(b*4 + c)*3*HWSZ + pix;
        mv[c] = g_part[base + 0*HWSZ];
        sv[c] = g_part[base + 1*HWSZ];
        tv[c] = g_part[base + 2*HWSZ];
        M = fmaxf(M, mv[c]);
    }
    float S = 0.0f, T = 0.0f;
    #pragma unroll
    for (int c = 0; c < 4; c++) {
        float sc = __expf(mv[c] - M);
        S += sv[c] * sc;
        T += tv[c] * sc;
    }
    out[idx] = __fdividef(T, S);
}

// ---------------------------------------------------------------------------
extern "C" void kernel_launch(void* const* d_in, const int* in_sizes, int n_in,
                              void* d_out, int out_size) {
    const float* features   = (const float*)d_in[0];
    const float* intrinsics = (const float*)d_in[1];
    const float* cam2world  = (const float*)d_in[2];
    const float* depth_hypo = (const float*)d_in[3];
    float* out = (float*)d_out;

    proj_kernel<<<1, 32>>>(intrinsics, cam2world);

    {
        int n = VV*BB*HWSZ;
        nhwc_kernel<<<(n + 255)/256, 256>>>(features);
    }
    {
        dim3 g(WW/TS, HH/TS, BB);
        wfeat_kernel<<<g, 256>>>();
    }
    {
        int n = BB*(DD/2)*HWSZ;
        warp_cost_kernel<<<(n + 255)/256, 256>>>(depth_hypo);
    }
    {
        dim3 g(WW/TS, HH/TS, BB*4);
        agg_part_kernel<<<g, 256>>>(depth_hypo);
    }
    {
        int n = BB*HWSZ;
        combine_kernel<<<(n + 255)/256, 256>>>(out);
    }
}